// round 2
// baseline (speedup 1.0000x reference)
#include <cuda_runtime.h>
#include <cuda_bf16.h>
#include <cstddef>

// Problem constants (fixed by the dataset)
constexpr int M = 100000;         // nodes
constexpr int K = 512;            // in_dim
constexpr int N = 128;            // out_dim
constexpr int E = 3200000;        // edges

// Device-global scratch (no allocations allowed).
__device__ float g_xp[(size_t)M * N];     // 51.2 MB  : xp = x @ W
__device__ int   g_cnt[M];                // degree histogram
__device__ int   g_rowptr[M];             // CSR row starts
__device__ int   g_cursor[M];             // fill cursors
__device__ int2  g_edges[E];              // packed {col, val-bits} in CSR order

// ---------------------------------------------------------------------------
// 1) zero the histogram
// ---------------------------------------------------------------------------
__global__ void zero_cnt_kernel(int* __restrict__ cnt) {
    int i = blockIdx.x * blockDim.x + threadIdx.x;
    if (i < M) cnt[i] = 0;
}

// ---------------------------------------------------------------------------
// 2) degree histogram over edge_row
// ---------------------------------------------------------------------------
__global__ void hist_kernel(const int* __restrict__ erow, int* __restrict__ cnt) {
    int i = blockIdx.x * blockDim.x + threadIdx.x;
    if (i < E) atomicAdd(&cnt[erow[i]], 1);
}

// ---------------------------------------------------------------------------
// 3) exclusive scan of cnt -> rowptr and cursor (single block, chunked)
// ---------------------------------------------------------------------------
__global__ void scan_kernel(const int* __restrict__ cnt,
                            int* __restrict__ rowptr,
                            int* __restrict__ cursor) {
    __shared__ int sh[1024];
    __shared__ int carry;
    const int tid = threadIdx.x;
    if (tid == 0) carry = 0;
    __syncthreads();

    for (int base = 0; base < M; base += 1024) {
        int i = base + tid;
        int v = (i < M) ? cnt[i] : 0;
        sh[tid] = v;
        __syncthreads();
        // Hillis-Steele inclusive scan
        for (int off = 1; off < 1024; off <<= 1) {
            int t = (tid >= off) ? sh[tid - off] : 0;
            __syncthreads();
            sh[tid] += t;
            __syncthreads();
        }
        int excl = sh[tid] - v;
        if (i < M) {
            int s = carry + excl;
            rowptr[i] = s;
            cursor[i] = s;
        }
        __syncthreads();
        if (tid == 1023) carry += sh[1023];
        __syncthreads();
    }
}

// ---------------------------------------------------------------------------
// 4) fill CSR: scatter each edge into its row segment, packing {col, val}
// ---------------------------------------------------------------------------
__global__ void fill_kernel(const int* __restrict__ erow,
                            const int* __restrict__ ecol,
                            const float* __restrict__ eval,
                            int* __restrict__ cursor,
                            int2* __restrict__ edges) {
    int i = blockIdx.x * blockDim.x + threadIdx.x;
    if (i >= E) return;
    int r = erow[i];
    int pos = atomicAdd(&cursor[r], 1);
    edges[pos] = make_int2(ecol[i], __float_as_int(eval[i]));
}

// ---------------------------------------------------------------------------
// 5) SGEMM  xp[M,N] = X[M,K] @ W[K,N]
// 128x128 block tile, BK=16, 256 threads, 8x8 register micro-tile per thread.
// ---------------------------------------------------------------------------
__global__ __launch_bounds__(256, 2)
void gemm_kernel(const float* __restrict__ X, const float* __restrict__ W,
                 float* __restrict__ XP) {
    __shared__ float As[16][128];   // [kk][row]  (A stored transposed)
    __shared__ float Bs[16][128];   // [kk][col]

    const int tid = threadIdx.x;
    const int ty = tid >> 4;        // 0..15
    const int tx = tid & 15;        // 0..15
    const int rowBase = blockIdx.x * 128;

    float acc[8][8];
#pragma unroll
    for (int i = 0; i < 8; i++)
#pragma unroll
        for (int j = 0; j < 8; j++) acc[i][j] = 0.0f;

    const int aRow = tid >> 2;          // 0..63
    const int aK   = (tid & 3) * 4;     // 0,4,8,12
    const int bK   = tid >> 5;          // 0..7
    const int bCol = (tid & 31) * 4;    // 0..124

    for (int k0 = 0; k0 < K; k0 += 16) {
#pragma unroll
        for (int s = 0; s < 2; s++) {
            int r = rowBase + aRow + s * 64;
            float4 v = make_float4(0.f, 0.f, 0.f, 0.f);
            if (r < M)
                v = *reinterpret_cast<const float4*>(&X[(size_t)r * K + k0 + aK]);
            As[aK + 0][aRow + s * 64] = v.x;
            As[aK + 1][aRow + s * 64] = v.y;
            As[aK + 2][aRow + s * 64] = v.z;
            As[aK + 3][aRow + s * 64] = v.w;
        }
#pragma unroll
        for (int s = 0; s < 2; s++) {
            int kk = bK + s * 8;
            float4 v = *reinterpret_cast<const float4*>(&W[(size_t)(k0 + kk) * N + bCol]);
            *reinterpret_cast<float4*>(&Bs[kk][bCol]) = v;
        }
        __syncthreads();

#pragma unroll
        for (int kk = 0; kk < 16; kk++) {
            float a[8], b[8];
#pragma unroll
            for (int i = 0; i < 8; i++) a[i] = As[kk][ty * 8 + i];
#pragma unroll
            for (int j = 0; j < 8; j++) b[j] = Bs[kk][tx * 8 + j];
#pragma unroll
            for (int i = 0; i < 8; i++)
#pragma unroll
                for (int j = 0; j < 8; j++) acc[i][j] += a[i] * b[j];
        }
        __syncthreads();
    }

#pragma unroll
    for (int i = 0; i < 8; i++) {
        int r = rowBase + ty * 8 + i;
        if (r < M) {
#pragma unroll
            for (int j = 0; j < 8; j += 4) {
                float4 v = make_float4(acc[i][j], acc[i][j + 1],
                                       acc[i][j + 2], acc[i][j + 3]);
                *reinterpret_cast<float4*>(&XP[(size_t)r * N + tx * 8 + j]) = v;
            }
        }
    }
}

// ---------------------------------------------------------------------------
// 6) gather-reduce + ReLU: one warp per output row, 4 cols per lane (float4).
//    No atomics; single coalesced store per row.
// ---------------------------------------------------------------------------
__global__ __launch_bounds__(256)
void gather_kernel(const int* __restrict__ rowptr,
                   const int* __restrict__ cnt,
                   const int2* __restrict__ edges,
                   const float* __restrict__ xp,
                   float* __restrict__ out) {
    int warp = (blockIdx.x * blockDim.x + threadIdx.x) >> 5;
    if (warp >= M) return;
    int lane = threadIdx.x & 31;

    int start = rowptr[warp];
    int deg   = cnt[warp];

    float4 acc = make_float4(0.f, 0.f, 0.f, 0.f);
    for (int t = 0; t < deg; t++) {
        int2 ev = edges[start + t];          // broadcast load (warp-uniform)
        int   c = ev.x;
        float v = __int_as_float(ev.y);
        float4 p = *reinterpret_cast<const float4*>(
            &xp[(size_t)c * N + lane * 4]);
        acc.x = fmaf(v, p.x, acc.x);
        acc.y = fmaf(v, p.y, acc.y);
        acc.z = fmaf(v, p.z, acc.z);
        acc.w = fmaf(v, p.w, acc.w);
    }
    float4 r = make_float4(fmaxf(acc.x, 0.f), fmaxf(acc.y, 0.f),
                           fmaxf(acc.z, 0.f), fmaxf(acc.w, 0.f));
    *reinterpret_cast<float4*>(&out[(size_t)warp * N + lane * 4]) = r;
}

// ---------------------------------------------------------------------------
extern "C" void kernel_launch(void* const* d_in, const int* in_sizes, int n_in,
                              void* d_out, int out_size) {
    const float* x    = (const float*)d_in[0];   // [M,K]
    const float* W    = (const float*)d_in[1];   // [K,N]
    const int*   erow = (const int*)d_in[2];     // [E]
    const int*   ecol = (const int*)d_in[3];     // [E]
    const float* eval = (const float*)d_in[4];   // [E]
    float* out = (float*)d_out;                  // [M,N]

    float* xp;     cudaGetSymbolAddress((void**)&xp,     g_xp);
    int*   cnt;    cudaGetSymbolAddress((void**)&cnt,    g_cnt);
    int*   rowptr; cudaGetSymbolAddress((void**)&rowptr, g_rowptr);
    int*   cursor; cudaGetSymbolAddress((void**)&cursor, g_cursor);
    int2*  edges;  cudaGetSymbolAddress((void**)&edges,  g_edges);

    // CSR build
    zero_cnt_kernel<<<(M + 255) / 256, 256>>>(cnt);
    hist_kernel<<<(E + 255) / 256, 256>>>(erow, cnt);
    scan_kernel<<<1, 1024>>>(cnt, rowptr, cursor);
    fill_kernel<<<(E + 255) / 256, 256>>>(erow, ecol, eval, cursor, edges);

    // Dense projection
    gemm_kernel<<<(M + 127) / 128, 256>>>(x, W, xp);

    // Aggregate + ReLU (one warp per row; 8 warps per 256-thread block)
    {
        int warpsPerBlock = 256 / 32;
        int blocks = (M + warpsPerBlock - 1) / warpsPerBlock;  // 12500
        gather_kernel<<<blocks, 256>>>(rowptr, cnt, edges, xp, out);
    }
}

// round 6
// speedup vs baseline: 1.4635x; 1.4635x over previous
#include <cuda_runtime.h>
#include <cuda_bf16.h>
#include <cstddef>

// Problem constants (fixed by the dataset)
constexpr int M = 100000;         // nodes
constexpr int K = 512;            // in_dim
constexpr int N = 128;            // out_dim
constexpr int E = 3200000;        // edges

// Device-global scratch (no allocations allowed).
__device__ float g_xp[(size_t)M * N];     // 51.2 MB  : xp = x @ W
__device__ int   g_cnt[M];                // degree histogram
__device__ int   g_rowptr[M];             // CSR row starts
__device__ int   g_cursor[M];             // fill cursors
__device__ int2  g_edges[E];              // packed {col, val-bits} in CSR order

// ---------------------------------------------------------------------------
// 1) zero the histogram
// ---------------------------------------------------------------------------
__global__ void zero_cnt_kernel(int* __restrict__ cnt) {
    int i = blockIdx.x * blockDim.x + threadIdx.x;
    if (i < M) cnt[i] = 0;
}

// ---------------------------------------------------------------------------
// 2) degree histogram over edge_row
// ---------------------------------------------------------------------------
__global__ void hist_kernel(const int* __restrict__ erow, int* __restrict__ cnt) {
    int i = blockIdx.x * blockDim.x + threadIdx.x;
    if (i < E) atomicAdd(&cnt[erow[i]], 1);
}

// ---------------------------------------------------------------------------
// 3) exclusive scan: 1024 threads, each owns a contiguous segment.
//    Phase A: per-thread segment sum. Phase B: block scan of 1024 partials.
//    Phase C: per-thread sequential prefix write-back.
// ---------------------------------------------------------------------------
__global__ void scan_kernel(const int* __restrict__ cnt,
                            int* __restrict__ rowptr,
                            int* __restrict__ cursor) {
    __shared__ int sh[1024];
    const int tid = threadIdx.x;
    const int seg = (M + 1023) / 1024;           // 98
    const int base = tid * seg;
    const int end = min(M, base + seg);

    int s = 0;
    for (int i = base; i < end; i++) s += cnt[i];
    sh[tid] = s;
    __syncthreads();

    // Hillis-Steele inclusive scan of the 1024 partials
    int v = s;
#pragma unroll
    for (int off = 1; off < 1024; off <<= 1) {
        int t = (tid >= off) ? sh[tid - off] : 0;
        __syncthreads();
        v += t;
        sh[tid] = v;
        __syncthreads();
    }
    int running = v - s;   // exclusive prefix for this segment

    for (int i = base; i < end; i++) {
        rowptr[i] = running;
        cursor[i] = running;
        running += cnt[i];
    }
}

// ---------------------------------------------------------------------------
// 4) fill CSR: scatter each edge into its row segment, packing {col, val}
// ---------------------------------------------------------------------------
__global__ void fill_kernel(const int* __restrict__ erow,
                            const int* __restrict__ ecol,
                            const float* __restrict__ eval,
                            int* __restrict__ cursor,
                            int2* __restrict__ edges) {
    int i = blockIdx.x * blockDim.x + threadIdx.x;
    if (i >= E) return;
    int r = erow[i];
    int pos = atomicAdd(&cursor[r], 1);
    edges[pos] = make_int2(ecol[i], __float_as_int(eval[i]));
}

// ---------------------------------------------------------------------------
// 5) tf32 tensor-core GEMM  xp[M,N] = X[M,K] @ W[K,N]
//    BM=128, BN=128, BK=32. 256 threads = 8 warps (4 x 2), each warp 32x64.
//    mma.sync.aligned.m16n8k8.f32.tf32.tf32.f32, fp32 accumulate.
//    Smem strides 36 / 136 give conflict-free fragment loads.
// ---------------------------------------------------------------------------
__device__ __forceinline__ unsigned f2tf32(float f) {
    unsigned u;
    asm("cvt.rna.tf32.f32 %0, %1;" : "=r"(u) : "f"(f));
    return u;
}

#define AS_STRIDE 36
#define BS_STRIDE 136

__global__ __launch_bounds__(256, 2)
void gemm_kernel(const float* __restrict__ X, const float* __restrict__ W,
                 float* __restrict__ XP) {
    __shared__ unsigned As[128 * AS_STRIDE];   // [m][k] padded
    __shared__ unsigned Bs[32 * BS_STRIDE];    // [k][n] padded

    const int tid = threadIdx.x;
    const int lane = tid & 31;
    const int warpId = tid >> 5;
    const int warpM = warpId & 3;     // 0..3 -> 32-row slab
    const int warpN = warpId >> 2;    // 0..1 -> 64-col slab
    const int rowBlock = blockIdx.x * 128;

    float acc[2][8][4];
#pragma unroll
    for (int i = 0; i < 2; i++)
#pragma unroll
        for (int j = 0; j < 8; j++)
#pragma unroll
            for (int c = 0; c < 4; c++) acc[i][j][c] = 0.0f;

    const int quad = lane >> 2;       // 0..7
    const int qlan = lane & 3;        // 0..3

    for (int k0 = 0; k0 < K; k0 += 32) {
        // --- load A tile: 128 rows x 32 k = 1024 float4, 4 per thread ---
#pragma unroll
        for (int it = 0; it < 4; it++) {
            int idx = tid + it * 256;          // 0..1023
            int r = idx >> 3;                  // 0..127
            int kq = idx & 7;                  // 0..7 (float4 within row)
            int gr = rowBlock + r;
            float4 v = make_float4(0.f, 0.f, 0.f, 0.f);
            if (gr < M)
                v = *reinterpret_cast<const float4*>(&X[(size_t)gr * K + k0 + kq * 4]);
            uint4 t = make_uint4(f2tf32(v.x), f2tf32(v.y), f2tf32(v.z), f2tf32(v.w));
            *reinterpret_cast<uint4*>(&As[r * AS_STRIDE + kq * 4]) = t;
        }
        // --- load B tile: 32 k-rows x 128 cols = 1024 float4 ---
#pragma unroll
        for (int it = 0; it < 4; it++) {
            int idx = tid + it * 256;
            int kr = idx >> 5;                 // 0..31
            int n4 = idx & 31;                 // 0..31
            float4 v = *reinterpret_cast<const float4*>(&W[(size_t)(k0 + kr) * N + n4 * 4]);
            uint4 t = make_uint4(f2tf32(v.x), f2tf32(v.y), f2tf32(v.z), f2tf32(v.w));
            *reinterpret_cast<uint4*>(&Bs[kr * BS_STRIDE + n4 * 4]) = t;
        }
        __syncthreads();

#pragma unroll
        for (int kk = 0; kk < 32; kk += 8) {
            // B fragments: 8 n-tiles of n8k8
            unsigned bf[8][2];
#pragma unroll
            for (int j = 0; j < 8; j++) {
                int col = warpN * 64 + j * 8 + quad;
                bf[j][0] = Bs[(kk + qlan) * BS_STRIDE + col];
                bf[j][1] = Bs[(kk + qlan + 4) * BS_STRIDE + col];
            }
            // A fragments: 2 m-tiles of m16k8
#pragma unroll
            for (int i = 0; i < 2; i++) {
                int row = warpM * 32 + i * 16 + quad;
                unsigned a0 = As[row * AS_STRIDE + kk + qlan];
                unsigned a1 = As[(row + 8) * AS_STRIDE + kk + qlan];
                unsigned a2 = As[row * AS_STRIDE + kk + qlan + 4];
                unsigned a3 = As[(row + 8) * AS_STRIDE + kk + qlan + 4];
#pragma unroll
                for (int j = 0; j < 8; j++) {
                    asm volatile(
                        "mma.sync.aligned.m16n8k8.row.col.f32.tf32.tf32.f32 "
                        "{%0,%1,%2,%3}, {%4,%5,%6,%7}, {%8,%9}, {%0,%1,%2,%3};\n"
                        : "+f"(acc[i][j][0]), "+f"(acc[i][j][1]),
                          "+f"(acc[i][j][2]), "+f"(acc[i][j][3])
                        : "r"(a0), "r"(a1), "r"(a2), "r"(a3),
                          "r"(bf[j][0]), "r"(bf[j][1]));
                }
            }
        }
        __syncthreads();
    }

    // Epilogue: write fp32 results
#pragma unroll
    for (int i = 0; i < 2; i++) {
        int row0 = rowBlock + warpM * 32 + i * 16 + quad;
        int row1 = row0 + 8;
#pragma unroll
        for (int j = 0; j < 8; j++) {
            int col = warpN * 64 + j * 8 + qlan * 2;
            if (row0 < M)
                *reinterpret_cast<float2*>(&XP[(size_t)row0 * N + col]) =
                    make_float2(acc[i][j][0], acc[i][j][1]);
            if (row1 < M)
                *reinterpret_cast<float2*>(&XP[(size_t)row1 * N + col]) =
                    make_float2(acc[i][j][2], acc[i][j][3]);
        }
    }
}

// ---------------------------------------------------------------------------
// 6) gather-reduce + ReLU: one warp per output row, 4 cols per lane (float4).
// ---------------------------------------------------------------------------
__global__ __launch_bounds__(256)
void gather_kernel(const int* __restrict__ rowptr,
                   const int* __restrict__ cnt,
                   const int2* __restrict__ edges,
                   const float* __restrict__ xp,
                   float* __restrict__ out) {
    int warp = (blockIdx.x * blockDim.x + threadIdx.x) >> 5;
    if (warp >= M) return;
    int lane = threadIdx.x & 31;

    int start = rowptr[warp];
    int deg   = cnt[warp];

    float4 acc = make_float4(0.f, 0.f, 0.f, 0.f);
    for (int t = 0; t < deg; t++) {
        int2 ev = edges[start + t];          // warp-uniform broadcast
        int   c = ev.x;
        float v = __int_as_float(ev.y);
        float4 p = *reinterpret_cast<const float4*>(
            &xp[(size_t)c * N + lane * 4]);
        acc.x = fmaf(v, p.x, acc.x);
        acc.y = fmaf(v, p.y, acc.y);
        acc.z = fmaf(v, p.z, acc.z);
        acc.w = fmaf(v, p.w, acc.w);
    }
    float4 r = make_float4(fmaxf(acc.x, 0.f), fmaxf(acc.y, 0.f),
                           fmaxf(acc.z, 0.f), fmaxf(acc.w, 0.f));
    *reinterpret_cast<float4*>(&out[(size_t)warp * N + lane * 4]) = r;
}

// ---------------------------------------------------------------------------
extern "C" void kernel_launch(void* const* d_in, const int* in_sizes, int n_in,
                              void* d_out, int out_size) {
    const float* x    = (const float*)d_in[0];   // [M,K]
    const float* W    = (const float*)d_in[1];   // [K,N]
    const int*   erow = (const int*)d_in[2];     // [E]
    const int*   ecol = (const int*)d_in[3];     // [E]
    const float* eval = (const float*)d_in[4];   // [E]
    float* out = (float*)d_out;                  // [M,N]

    float* xp;     cudaGetSymbolAddress((void**)&xp,     g_xp);
    int*   cnt;    cudaGetSymbolAddress((void**)&cnt,    g_cnt);
    int*   rowptr; cudaGetSymbolAddress((void**)&rowptr, g_rowptr);
    int*   cursor; cudaGetSymbolAddress((void**)&cursor, g_cursor);
    int2*  edges;  cudaGetSymbolAddress((void**)&edges,  g_edges);

    // CSR build
    zero_cnt_kernel<<<(M + 255) / 256, 256>>>(cnt);
    hist_kernel<<<(E + 255) / 256, 256>>>(erow, cnt);
    scan_kernel<<<1, 1024>>>(cnt, rowptr, cursor);
    fill_kernel<<<(E + 255) / 256, 256>>>(erow, ecol, eval, cursor, edges);

    // Dense projection (tf32 tensor cores)
    gemm_kernel<<<(M + 127) / 128, 256>>>(x, W, xp);

    // Aggregate + ReLU (one warp per row; 8 warps per 256-thread block)
    {
        int warpsPerBlock = 256 / 32;
        int blocks = (M + warpsPerBlock - 1) / warpsPerBlock;  // 12500
        gather_kernel<<<blocks, 256>>>(rowptr, cnt, edges, xp, out);
    }
}

// round 7
// speedup vs baseline: 1.5081x; 1.0305x over previous
#include <cuda_runtime.h>
#include <cuda_bf16.h>
#include <cstddef>

// Problem constants (fixed by the dataset)
constexpr int M = 100000;         // nodes
constexpr int K = 512;            // in_dim
constexpr int N = 128;            // out_dim
constexpr int E = 3200000;        // edges

// Device-global scratch (no allocations allowed).
__device__ float g_xp[(size_t)M * N];     // 51.2 MB  : xp = x @ W
__device__ int   g_cnt[M];                // degree histogram
__device__ int   g_rowptr[M];             // CSR row starts
__device__ int   g_cursor[M];             // fill cursors
__device__ int2  g_edges[E];              // packed {col, val-bits} in CSR order

// ---------------------------------------------------------------------------
// 1) zero the histogram
// ---------------------------------------------------------------------------
__global__ void zero_cnt_kernel(int* __restrict__ cnt) {
    int i = blockIdx.x * blockDim.x + threadIdx.x;
    if (i < M) cnt[i] = 0;
}

// ---------------------------------------------------------------------------
// 2) degree histogram over edge_row
// ---------------------------------------------------------------------------
__global__ void hist_kernel(const int* __restrict__ erow, int* __restrict__ cnt) {
    int i = blockIdx.x * blockDim.x + threadIdx.x;
    if (i < E) atomicAdd(&cnt[erow[i]], 1);
}

// ---------------------------------------------------------------------------
// 3) exclusive scan: 1024 threads, each owns a contiguous segment.
// ---------------------------------------------------------------------------
__global__ void scan_kernel(const int* __restrict__ cnt,
                            int* __restrict__ rowptr,
                            int* __restrict__ cursor) {
    __shared__ int sh[1024];
    const int tid = threadIdx.x;
    const int seg = (M + 1023) / 1024;           // 98
    const int base = tid * seg;
    const int end = min(M, base + seg);

    int s = 0;
    for (int i = base; i < end; i++) s += cnt[i];
    sh[tid] = s;
    __syncthreads();

    int v = s;
#pragma unroll
    for (int off = 1; off < 1024; off <<= 1) {
        int t = (tid >= off) ? sh[tid - off] : 0;
        __syncthreads();
        v += t;
        sh[tid] = v;
        __syncthreads();
    }
    int running = v - s;   // exclusive prefix for this segment

    for (int i = base; i < end; i++) {
        rowptr[i] = running;
        cursor[i] = running;
        running += cnt[i];
    }
}

// ---------------------------------------------------------------------------
// 4) fill CSR: scatter each edge into its row segment, packing {col, val}
// ---------------------------------------------------------------------------
__global__ void fill_kernel(const int* __restrict__ erow,
                            const int* __restrict__ ecol,
                            const float* __restrict__ eval,
                            int* __restrict__ cursor,
                            int2* __restrict__ edges) {
    int i = blockIdx.x * blockDim.x + threadIdx.x;
    if (i >= E) return;
    int r = erow[i];
    int pos = atomicAdd(&cursor[r], 1);
    edges[pos] = make_int2(ecol[i], __float_as_int(eval[i]));
}

// ---------------------------------------------------------------------------
// 5) tf32 tensor-core GEMM  xp[M,N] = X[M,K] @ W[K,N]
//    BM=128, BN=128, BK=16. Double-buffered smem + register-staged prefetch:
//    exactly one __syncthreads per K-iteration; GMEM loads for tile i+1
//    overlap the MMAs of tile i. rn-rounded tf32 (unbiased), fp32 accumulate.
// ---------------------------------------------------------------------------
__device__ __forceinline__ unsigned f2tf32(float f) {
    unsigned u;
    asm("cvt.rna.tf32.f32 %0, %1;" : "=r"(u) : "f"(f));
    return u;
}

#define AS_STRIDE 20     // 16 k + 4 pad (floats); 80B rows, 16B aligned
#define BS_STRIDE 136    // 128 n + 8 pad

__global__ __launch_bounds__(256, 2)
void gemm_kernel(const float* __restrict__ X, const float* __restrict__ W,
                 float* __restrict__ XP) {
    __shared__ unsigned As[2][128 * AS_STRIDE];   // [m][k] padded
    __shared__ unsigned Bs[2][16 * BS_STRIDE];    // [k][n] padded

    const int tid = threadIdx.x;
    const int lane = tid & 31;
    const int warpId = tid >> 5;
    const int warpM = warpId & 3;     // 0..3 -> 32-row slab
    const int warpN = warpId >> 2;    // 0..1 -> 64-col slab
    const int rowBlock = blockIdx.x * 128;

    float acc[2][8][4];
#pragma unroll
    for (int i = 0; i < 2; i++)
#pragma unroll
        for (int j = 0; j < 8; j++)
#pragma unroll
            for (int c = 0; c < 4; c++) acc[i][j][c] = 0.0f;

    const int quad = lane >> 2;       // 0..7
    const int qlan = lane & 3;        // 0..3

    // Per-stage load mapping (2 float4 per thread for each of A and B):
    //  A: idx = tid + s*256 in [0,512): row = idx>>2, kq = idx&3
    //  B: kr = idx>>5 in [0,16), n4 = idx&31
    const int aRow0 = tid >> 2;            // rows for s=0
    const int aKq0  = tid & 3;
    const int aRow1 = (tid + 256) >> 2;    // rows for s=1
    const int aKq1  = (tid + 256) & 3;
    const int bKr0  = tid >> 5;
    const int bN4   = tid & 31;
    const int bKr1  = ((tid + 256) >> 5);  // = bKr0 + 8

    // helper lambdas as macros to keep everything in registers
    float4 aReg[2], bReg[2];

    // ---- prologue: load k0 = 0 tile into regs, convert, store stage 0 ----
    {
        int gr0 = rowBlock + aRow0;
        int gr1 = rowBlock + aRow1;
        aReg[0] = (gr0 < M) ? *reinterpret_cast<const float4*>(&X[(size_t)gr0 * K + aKq0 * 4])
                            : make_float4(0.f, 0.f, 0.f, 0.f);
        aReg[1] = (gr1 < M) ? *reinterpret_cast<const float4*>(&X[(size_t)gr1 * K + aKq1 * 4])
                            : make_float4(0.f, 0.f, 0.f, 0.f);
        bReg[0] = *reinterpret_cast<const float4*>(&W[(size_t)bKr0 * N + bN4 * 4]);
        bReg[1] = *reinterpret_cast<const float4*>(&W[(size_t)bKr1 * N + bN4 * 4]);

        *reinterpret_cast<uint4*>(&As[0][aRow0 * AS_STRIDE + aKq0 * 4]) =
            make_uint4(f2tf32(aReg[0].x), f2tf32(aReg[0].y), f2tf32(aReg[0].z), f2tf32(aReg[0].w));
        *reinterpret_cast<uint4*>(&As[0][aRow1 * AS_STRIDE + aKq1 * 4]) =
            make_uint4(f2tf32(aReg[1].x), f2tf32(aReg[1].y), f2tf32(aReg[1].z), f2tf32(aReg[1].w));
        *reinterpret_cast<uint4*>(&Bs[0][bKr0 * BS_STRIDE + bN4 * 4]) =
            make_uint4(f2tf32(bReg[0].x), f2tf32(bReg[0].y), f2tf32(bReg[0].z), f2tf32(bReg[0].w));
        *reinterpret_cast<uint4*>(&Bs[0][bKr1 * BS_STRIDE + bN4 * 4]) =
            make_uint4(f2tf32(bReg[1].x), f2tf32(bReg[1].y), f2tf32(bReg[1].z), f2tf32(bReg[1].w));
    }
    __syncthreads();

    const int NITER = K / 16;   // 32
    for (int it = 0; it < NITER; it++) {
        const int buf = it & 1;
        const int nxt = buf ^ 1;
        const int kNext = (it + 1) * 16;

        // ---- issue global loads for next tile (overlaps MMAs below) ----
        if (it + 1 < NITER) {
            int gr0 = rowBlock + aRow0;
            int gr1 = rowBlock + aRow1;
            aReg[0] = (gr0 < M) ? *reinterpret_cast<const float4*>(&X[(size_t)gr0 * K + kNext + aKq0 * 4])
                                : make_float4(0.f, 0.f, 0.f, 0.f);
            aReg[1] = (gr1 < M) ? *reinterpret_cast<const float4*>(&X[(size_t)gr1 * K + kNext + aKq1 * 4])
                                : make_float4(0.f, 0.f, 0.f, 0.f);
            bReg[0] = *reinterpret_cast<const float4*>(&W[(size_t)(kNext + bKr0) * N + bN4 * 4]);
            bReg[1] = *reinterpret_cast<const float4*>(&W[(size_t)(kNext + bKr1) * N + bN4 * 4]);
        }

        // ---- compute current tile: 2 kk-steps of k8 ----
#pragma unroll
        for (int kk = 0; kk < 16; kk += 8) {
            unsigned bf[8][2];
#pragma unroll
            for (int j = 0; j < 8; j++) {
                int col = warpN * 64 + j * 8 + quad;
                bf[j][0] = Bs[buf][(kk + qlan) * BS_STRIDE + col];
                bf[j][1] = Bs[buf][(kk + qlan + 4) * BS_STRIDE + col];
            }
#pragma unroll
            for (int i = 0; i < 2; i++) {
                int row = warpM * 32 + i * 16 + quad;
                unsigned a0 = As[buf][row * AS_STRIDE + kk + qlan];
                unsigned a1 = As[buf][(row + 8) * AS_STRIDE + kk + qlan];
                unsigned a2 = As[buf][row * AS_STRIDE + kk + qlan + 4];
                unsigned a3 = As[buf][(row + 8) * AS_STRIDE + kk + qlan + 4];
#pragma unroll
                for (int j = 0; j < 8; j++) {
                    asm volatile(
                        "mma.sync.aligned.m16n8k8.row.col.f32.tf32.tf32.f32 "
                        "{%0,%1,%2,%3}, {%4,%5,%6,%7}, {%8,%9}, {%0,%1,%2,%3};\n"
                        : "+f"(acc[i][j][0]), "+f"(acc[i][j][1]),
                          "+f"(acc[i][j][2]), "+f"(acc[i][j][3])
                        : "r"(a0), "r"(a1), "r"(a2), "r"(a3),
                          "r"(bf[j][0]), "r"(bf[j][1]));
                }
            }
        }

        // ---- convert + store next tile into the other buffer ----
        if (it + 1 < NITER) {
            *reinterpret_cast<uint4*>(&As[nxt][aRow0 * AS_STRIDE + aKq0 * 4]) =
                make_uint4(f2tf32(aReg[0].x), f2tf32(aReg[0].y), f2tf32(aReg[0].z), f2tf32(aReg[0].w));
            *reinterpret_cast<uint4*>(&As[nxt][aRow1 * AS_STRIDE + aKq1 * 4]) =
                make_uint4(f2tf32(aReg[1].x), f2tf32(aReg[1].y), f2tf32(aReg[1].z), f2tf32(aReg[1].w));
            *reinterpret_cast<uint4*>(&Bs[nxt][bKr0 * BS_STRIDE + bN4 * 4]) =
                make_uint4(f2tf32(bReg[0].x), f2tf32(bReg[0].y), f2tf32(bReg[0].z), f2tf32(bReg[0].w));
            *reinterpret_cast<uint4*>(&Bs[nxt][bKr1 * BS_STRIDE + bN4 * 4]) =
                make_uint4(f2tf32(bReg[1].x), f2tf32(bReg[1].y), f2tf32(bReg[1].z), f2tf32(bReg[1].w));
        }
        __syncthreads();
    }

    // Epilogue: write fp32 results
#pragma unroll
    for (int i = 0; i < 2; i++) {
        int row0 = rowBlock + warpM * 32 + i * 16 + quad;
        int row1 = row0 + 8;
#pragma unroll
        for (int j = 0; j < 8; j++) {
            int col = warpN * 64 + j * 8 + qlan * 2;
            if (row0 < M)
                *reinterpret_cast<float2*>(&XP[(size_t)row0 * N + col]) =
                    make_float2(acc[i][j][0], acc[i][j][1]);
            if (row1 < M)
                *reinterpret_cast<float2*>(&XP[(size_t)row1 * N + col]) =
                    make_float2(acc[i][j][2], acc[i][j][3]);
        }
    }
}

// ---------------------------------------------------------------------------
// 6) gather-reduce + ReLU: one warp per output row, 4 cols per lane (float4).
//    2-edge unroll with dual accumulators -> 2 independent L2 gathers in
//    flight per warp step.
// ---------------------------------------------------------------------------
__global__ __launch_bounds__(256)
void gather_kernel(const int* __restrict__ rowptr,
                   const int* __restrict__ cnt,
                   const int2* __restrict__ edges,
                   const float* __restrict__ xp,
                   float* __restrict__ out) {
    int warp = (blockIdx.x * blockDim.x + threadIdx.x) >> 5;
    if (warp >= M) return;
    int lane = threadIdx.x & 31;

    int start = rowptr[warp];
    int deg   = cnt[warp];

    float4 acc0 = make_float4(0.f, 0.f, 0.f, 0.f);
    float4 acc1 = make_float4(0.f, 0.f, 0.f, 0.f);

    int t = 0;
    for (; t + 1 < deg; t += 2) {
        int2 ev0 = edges[start + t];
        int2 ev1 = edges[start + t + 1];
        float v0 = __int_as_float(ev0.y);
        float v1 = __int_as_float(ev1.y);
        float4 p0 = *reinterpret_cast<const float4*>(&xp[(size_t)ev0.x * N + lane * 4]);
        float4 p1 = *reinterpret_cast<const float4*>(&xp[(size_t)ev1.x * N + lane * 4]);
        acc0.x = fmaf(v0, p0.x, acc0.x);
        acc0.y = fmaf(v0, p0.y, acc0.y);
        acc0.z = fmaf(v0, p0.z, acc0.z);
        acc0.w = fmaf(v0, p0.w, acc0.w);
        acc1.x = fmaf(v1, p1.x, acc1.x);
        acc1.y = fmaf(v1, p1.y, acc1.y);
        acc1.z = fmaf(v1, p1.z, acc1.z);
        acc1.w = fmaf(v1, p1.w, acc1.w);
    }
    if (t < deg) {
        int2 ev = edges[start + t];
        float v = __int_as_float(ev.y);
        float4 p = *reinterpret_cast<const float4*>(&xp[(size_t)ev.x * N + lane * 4]);
        acc0.x = fmaf(v, p.x, acc0.x);
        acc0.y = fmaf(v, p.y, acc0.y);
        acc0.z = fmaf(v, p.z, acc0.z);
        acc0.w = fmaf(v, p.w, acc0.w);
    }

    float4 r = make_float4(fmaxf(acc0.x + acc1.x, 0.f),
                           fmaxf(acc0.y + acc1.y, 0.f),
                           fmaxf(acc0.z + acc1.z, 0.f),
                           fmaxf(acc0.w + acc1.w, 0.f));
    *reinterpret_cast<float4*>(&out[(size_t)warp * N + lane * 4]) = r;
}

// ---------------------------------------------------------------------------
extern "C" void kernel_launch(void* const* d_in, const int* in_sizes, int n_in,
                              void* d_out, int out_size) {
    const float* x    = (const float*)d_in[0];   // [M,K]
    const float* W    = (const float*)d_in[1];   // [K,N]
    const int*   erow = (const int*)d_in[2];     // [E]
    const int*   ecol = (const int*)d_in[3];     // [E]
    const float* eval = (const float*)d_in[4];   // [E]
    float* out = (float*)d_out;                  // [M,N]

    float* xp;     cudaGetSymbolAddress((void**)&xp,     g_xp);
    int*   cnt;    cudaGetSymbolAddress((void**)&cnt,    g_cnt);
    int*   rowptr; cudaGetSymbolAddress((void**)&rowptr, g_rowptr);
    int*   cursor; cudaGetSymbolAddress((void**)&cursor, g_cursor);
    int2*  edges;  cudaGetSymbolAddress((void**)&edges,  g_edges);

    // CSR build
    zero_cnt_kernel<<<(M + 255) / 256, 256>>>(cnt);
    hist_kernel<<<(E + 255) / 256, 256>>>(erow, cnt);
    scan_kernel<<<1, 1024>>>(cnt, rowptr, cursor);
    fill_kernel<<<(E + 255) / 256, 256>>>(erow, ecol, eval, cursor, edges);

    // Dense projection (tf32 tensor cores, double-buffered)
    gemm_kernel<<<(M + 127) / 128, 256>>>(x, W, xp);

    // Aggregate + ReLU (one warp per row; 8 warps per 256-thread block)
    {
        int warpsPerBlock = 256 / 32;
        int blocks = (M + warpsPerBlock - 1) / warpsPerBlock;  // 12500
        gather_kernel<<<blocks, 256>>>(rowptr, cnt, edges, xp, out);
    }
}

// round 9
// speedup vs baseline: 1.5469x; 1.0257x over previous
#include <cuda_runtime.h>
#include <cuda_bf16.h>
#include <cuda_fp16.h>
#include <cstddef>
#include <cstdint>

// Problem constants (fixed by the dataset)
constexpr int M = 100000;         // nodes
constexpr int K = 512;            // in_dim
constexpr int N = 128;            // out_dim
constexpr int E = 3200000;        // edges

// Device-global scratch (no allocations allowed).
__device__ __half g_xph[(size_t)M * N];   // 25.6 MB : xp = x @ W in fp16
__device__ int   g_cnt[M];                // degree histogram
__device__ int   g_rowptr[M];             // CSR row starts
__device__ int   g_cursor[M];             // fill cursors
__device__ int2  g_edges[E];              // packed {col, val-bits} in CSR order

// ---------------------------------------------------------------------------
// 1) zero the histogram
// ---------------------------------------------------------------------------
__global__ void zero_cnt_kernel(int* __restrict__ cnt) {
    int i = blockIdx.x * blockDim.x + threadIdx.x;
    if (i < M) cnt[i] = 0;
}

// ---------------------------------------------------------------------------
// 2) degree histogram over edge_row
// ---------------------------------------------------------------------------
__global__ void hist_kernel(const int* __restrict__ erow, int* __restrict__ cnt) {
    int i = blockIdx.x * blockDim.x + threadIdx.x;
    if (i < E) atomicAdd(&cnt[erow[i]], 1);
}

// ---------------------------------------------------------------------------
// 3) exclusive scan: 1024 threads, each owns a contiguous segment.
// ---------------------------------------------------------------------------
__global__ void scan_kernel(const int* __restrict__ cnt,
                            int* __restrict__ rowptr,
                            int* __restrict__ cursor) {
    __shared__ int sh[1024];
    const int tid = threadIdx.x;
    const int seg = (M + 1023) / 1024;           // 98
    const int base = tid * seg;
    const int end = min(M, base + seg);

    int s = 0;
    for (int i = base; i < end; i++) s += cnt[i];
    sh[tid] = s;
    __syncthreads();

    int v = s;
#pragma unroll
    for (int off = 1; off < 1024; off <<= 1) {
        int t = (tid >= off) ? sh[tid - off] : 0;
        __syncthreads();
        v += t;
        sh[tid] = v;
        __syncthreads();
    }
    int running = v - s;   // exclusive prefix for this segment

    for (int i = base; i < end; i++) {
        rowptr[i] = running;
        cursor[i] = running;
        running += cnt[i];
    }
}

// ---------------------------------------------------------------------------
// 4) fill CSR: scatter each edge into its row segment, packing {col, val}
// ---------------------------------------------------------------------------
__global__ void fill_kernel(const int* __restrict__ erow,
                            const int* __restrict__ ecol,
                            const float* __restrict__ eval,
                            int* __restrict__ cursor,
                            int2* __restrict__ edges) {
    int i = blockIdx.x * blockDim.x + threadIdx.x;
    if (i >= E) return;
    int r = erow[i];
    int pos = atomicAdd(&cursor[r], 1);
    edges[pos] = make_int2(ecol[i], __float_as_int(eval[i]));
}

// ---------------------------------------------------------------------------
// 5) tf32 tensor-core GEMM  xp[M,N] = X[M,K] @ W[K,N], fp16 output.
//    BM=128, BN=128, BK=16. Double-buffered smem + register-staged prefetch.
// ---------------------------------------------------------------------------
__device__ __forceinline__ unsigned f2tf32(float f) {
    unsigned u;
    asm("cvt.rna.tf32.f32 %0, %1;" : "=r"(u) : "f"(f));
    return u;
}

#define AS_STRIDE 20     // 16 k + 4 pad (floats); 80B rows, 16B aligned
#define BS_STRIDE 136    // 128 n + 8 pad

__global__ __launch_bounds__(256, 2)
void gemm_kernel(const float* __restrict__ X, const float* __restrict__ W,
                 __half* __restrict__ XPh) {
    __shared__ unsigned As[2][128 * AS_STRIDE];   // [m][k] padded
    __shared__ unsigned Bs[2][16 * BS_STRIDE];    // [k][n] padded

    const int tid = threadIdx.x;
    const int lane = tid & 31;
    const int warpId = tid >> 5;
    const int warpM = warpId & 3;     // 0..3 -> 32-row slab
    const int warpN = warpId >> 2;    // 0..1 -> 64-col slab
    const int rowBlock = blockIdx.x * 128;

    float acc[2][8][4];
#pragma unroll
    for (int i = 0; i < 2; i++)
#pragma unroll
        for (int j = 0; j < 8; j++)
#pragma unroll
            for (int c = 0; c < 4; c++) acc[i][j][c] = 0.0f;

    const int quad = lane >> 2;       // 0..7
    const int qlan = lane & 3;        // 0..3

    const int aRow0 = tid >> 2;            // rows for s=0
    const int aKq0  = tid & 3;
    const int aRow1 = (tid + 256) >> 2;    // rows for s=1
    const int aKq1  = (tid + 256) & 3;
    const int bKr0  = tid >> 5;
    const int bN4   = tid & 31;
    const int bKr1  = ((tid + 256) >> 5);  // = bKr0 + 8

    float4 aReg[2], bReg[2];

    // ---- prologue: load k0 = 0 tile into regs, convert, store stage 0 ----
    {
        int gr0 = rowBlock + aRow0;
        int gr1 = rowBlock + aRow1;
        aReg[0] = (gr0 < M) ? *reinterpret_cast<const float4*>(&X[(size_t)gr0 * K + aKq0 * 4])
                            : make_float4(0.f, 0.f, 0.f, 0.f);
        aReg[1] = (gr1 < M) ? *reinterpret_cast<const float4*>(&X[(size_t)gr1 * K + aKq1 * 4])
                            : make_float4(0.f, 0.f, 0.f, 0.f);
        bReg[0] = *reinterpret_cast<const float4*>(&W[(size_t)bKr0 * N + bN4 * 4]);
        bReg[1] = *reinterpret_cast<const float4*>(&W[(size_t)bKr1 * N + bN4 * 4]);

        *reinterpret_cast<uint4*>(&As[0][aRow0 * AS_STRIDE + aKq0 * 4]) =
            make_uint4(f2tf32(aReg[0].x), f2tf32(aReg[0].y), f2tf32(aReg[0].z), f2tf32(aReg[0].w));
        *reinterpret_cast<uint4*>(&As[0][aRow1 * AS_STRIDE + aKq1 * 4]) =
            make_uint4(f2tf32(aReg[1].x), f2tf32(aReg[1].y), f2tf32(aReg[1].z), f2tf32(aReg[1].w));
        *reinterpret_cast<uint4*>(&Bs[0][bKr0 * BS_STRIDE + bN4 * 4]) =
            make_uint4(f2tf32(bReg[0].x), f2tf32(bReg[0].y), f2tf32(bReg[0].z), f2tf32(bReg[0].w));
        *reinterpret_cast<uint4*>(&Bs[0][bKr1 * BS_STRIDE + bN4 * 4]) =
            make_uint4(f2tf32(bReg[1].x), f2tf32(bReg[1].y), f2tf32(bReg[1].z), f2tf32(bReg[1].w));
    }
    __syncthreads();

    const int NITER = K / 16;   // 32
    for (int it = 0; it < NITER; it++) {
        const int buf = it & 1;
        const int nxt = buf ^ 1;
        const int kNext = (it + 1) * 16;

        // ---- issue global loads for next tile (overlaps MMAs below) ----
        if (it + 1 < NITER) {
            int gr0 = rowBlock + aRow0;
            int gr1 = rowBlock + aRow1;
            aReg[0] = (gr0 < M) ? *reinterpret_cast<const float4*>(&X[(size_t)gr0 * K + kNext + aKq0 * 4])
                                : make_float4(0.f, 0.f, 0.f, 0.f);
            aReg[1] = (gr1 < M) ? *reinterpret_cast<const float4*>(&X[(size_t)gr1 * K + kNext + aKq1 * 4])
                                : make_float4(0.f, 0.f, 0.f, 0.f);
            bReg[0] = *reinterpret_cast<const float4*>(&W[(size_t)(kNext + bKr0) * N + bN4 * 4]);
            bReg[1] = *reinterpret_cast<const float4*>(&W[(size_t)(kNext + bKr1) * N + bN4 * 4]);
        }

        // ---- compute current tile: 2 kk-steps of k8 ----
#pragma unroll
        for (int kk = 0; kk < 16; kk += 8) {
            unsigned bf[8][2];
#pragma unroll
            for (int j = 0; j < 8; j++) {
                int col = warpN * 64 + j * 8 + quad;
                bf[j][0] = Bs[buf][(kk + qlan) * BS_STRIDE + col];
                bf[j][1] = Bs[buf][(kk + qlan + 4) * BS_STRIDE + col];
            }
#pragma unroll
            for (int i = 0; i < 2; i++) {
                int row = warpM * 32 + i * 16 + quad;
                unsigned a0 = As[buf][row * AS_STRIDE + kk + qlan];
                unsigned a1 = As[buf][(row + 8) * AS_STRIDE + kk + qlan];
                unsigned a2 = As[buf][row * AS_STRIDE + kk + qlan + 4];
                unsigned a3 = As[buf][(row + 8) * AS_STRIDE + kk + qlan + 4];
#pragma unroll
                for (int j = 0; j < 8; j++) {
                    asm volatile(
                        "mma.sync.aligned.m16n8k8.row.col.f32.tf32.tf32.f32 "
                        "{%0,%1,%2,%3}, {%4,%5,%6,%7}, {%8,%9}, {%0,%1,%2,%3};\n"
                        : "+f"(acc[i][j][0]), "+f"(acc[i][j][1]),
                          "+f"(acc[i][j][2]), "+f"(acc[i][j][3])
                        : "r"(a0), "r"(a1), "r"(a2), "r"(a3),
                          "r"(bf[j][0]), "r"(bf[j][1]));
                }
            }
        }

        // ---- convert + store next tile into the other buffer ----
        if (it + 1 < NITER) {
            *reinterpret_cast<uint4*>(&As[nxt][aRow0 * AS_STRIDE + aKq0 * 4]) =
                make_uint4(f2tf32(aReg[0].x), f2tf32(aReg[0].y), f2tf32(aReg[0].z), f2tf32(aReg[0].w));
            *reinterpret_cast<uint4*>(&As[nxt][aRow1 * AS_STRIDE + aKq1 * 4]) =
                make_uint4(f2tf32(aReg[1].x), f2tf32(aReg[1].y), f2tf32(aReg[1].z), f2tf32(aReg[1].w));
            *reinterpret_cast<uint4*>(&Bs[nxt][bKr0 * BS_STRIDE + bN4 * 4]) =
                make_uint4(f2tf32(bReg[0].x), f2tf32(bReg[0].y), f2tf32(bReg[0].z), f2tf32(bReg[0].w));
            *reinterpret_cast<uint4*>(&Bs[nxt][bKr1 * BS_STRIDE + bN4 * 4]) =
                make_uint4(f2tf32(bReg[1].x), f2tf32(bReg[1].y), f2tf32(bReg[1].z), f2tf32(bReg[1].w));
        }
        __syncthreads();
    }

    // Epilogue: write fp16 results (pairs are contiguous cols -> one __half2)
#pragma unroll
    for (int i = 0; i < 2; i++) {
        int row0 = rowBlock + warpM * 32 + i * 16 + quad;
        int row1 = row0 + 8;
#pragma unroll
        for (int j = 0; j < 8; j++) {
            int col = warpN * 64 + j * 8 + qlan * 2;
            if (row0 < M)
                *reinterpret_cast<__half2*>(&XPh[(size_t)row0 * N + col]) =
                    __floats2half2_rn(acc[i][j][0], acc[i][j][1]);
            if (row1 < M)
                *reinterpret_cast<__half2*>(&XPh[(size_t)row1 * N + col]) =
                    __floats2half2_rn(acc[i][j][2], acc[i][j][3]);
        }
    }
}

// ---------------------------------------------------------------------------
// 6) gather-reduce + ReLU: one warp per row, 4 fp16 cols per lane (uint2),
//    2-edge unroll with dual accumulators; fp32 accumulate; fp32 store.
// ---------------------------------------------------------------------------
__global__ __launch_bounds__(256)
void gather_kernel(const int* __restrict__ rowptr,
                   const int* __restrict__ cnt,
                   const int2* __restrict__ edges,
                   const __half* __restrict__ xp,
                   float* __restrict__ out) {
    int warp = (blockIdx.x * blockDim.x + threadIdx.x) >> 5;
    if (warp >= M) return;
    int lane = threadIdx.x & 31;

    int start = rowptr[warp];
    int deg   = cnt[warp];

    float4 acc0 = make_float4(0.f, 0.f, 0.f, 0.f);
    float4 acc1 = make_float4(0.f, 0.f, 0.f, 0.f);

    int t = 0;
    for (; t + 1 < deg; t += 2) {
        int2 ev0 = edges[start + t];
        int2 ev1 = edges[start + t + 1];
        float v0 = __int_as_float(ev0.y);
        float v1 = __int_as_float(ev1.y);
        uint2 u0 = *reinterpret_cast<const uint2*>(&xp[(size_t)ev0.x * N + lane * 4]);
        uint2 u1 = *reinterpret_cast<const uint2*>(&xp[(size_t)ev1.x * N + lane * 4]);
        float2 a0 = __half22float2(*reinterpret_cast<__half2*>(&u0.x));
        float2 b0 = __half22float2(*reinterpret_cast<__half2*>(&u0.y));
        float2 a1 = __half22float2(*reinterpret_cast<__half2*>(&u1.x));
        float2 b1 = __half22float2(*reinterpret_cast<__half2*>(&u1.y));
        acc0.x = fmaf(v0, a0.x, acc0.x);
        acc0.y = fmaf(v0, a0.y, acc0.y);
        acc0.z = fmaf(v0, b0.x, acc0.z);
        acc0.w = fmaf(v0, b0.y, acc0.w);
        acc1.x = fmaf(v1, a1.x, acc1.x);
        acc1.y = fmaf(v1, a1.y, acc1.y);
        acc1.z = fmaf(v1, b1.x, acc1.z);
        acc1.w = fmaf(v1, b1.y, acc1.w);
    }
    if (t < deg) {
        int2 ev = edges[start + t];
        float v = __int_as_float(ev.y);
        uint2 u = *reinterpret_cast<const uint2*>(&xp[(size_t)ev.x * N + lane * 4]);
        float2 a = __half22float2(*reinterpret_cast<__half2*>(&u.x));
        float2 b = __half22float2(*reinterpret_cast<__half2*>(&u.y));
        acc0.x = fmaf(v, a.x, acc0.x);
        acc0.y = fmaf(v, a.y, acc0.y);
        acc0.z = fmaf(v, b.x, acc0.z);
        acc0.w = fmaf(v, b.y, acc0.w);
    }

    float4 r = make_float4(fmaxf(acc0.x + acc1.x, 0.f),
                           fmaxf(acc0.y + acc1.y, 0.f),
                           fmaxf(acc0.z + acc1.z, 0.f),
                           fmaxf(acc0.w + acc1.w, 0.f));
    *reinterpret_cast<float4*>(&out[(size_t)warp * N + lane * 4]) = r;
}

// ---------------------------------------------------------------------------
extern "C" void kernel_launch(void* const* d_in, const int* in_sizes, int n_in,
                              void* d_out, int out_size) {
    const float* x    = (const float*)d_in[0];   // [M,K]
    const float* W    = (const float*)d_in[1];   // [K,N]
    const int*   erow = (const int*)d_in[2];     // [E]
    const int*   ecol = (const int*)d_in[3];     // [E]
    const float* eval = (const float*)d_in[4];   // [E]
    float* out = (float*)d_out;                  // [M,N]

    __half* xph;   cudaGetSymbolAddress((void**)&xph,    g_xph);
    int*  cnt;     cudaGetSymbolAddress((void**)&cnt,    g_cnt);
    int*  rowptr;  cudaGetSymbolAddress((void**)&rowptr, g_rowptr);
    int*  cursor;  cudaGetSymbolAddress((void**)&cursor, g_cursor);
    int2* edges;   cudaGetSymbolAddress((void**)&edges,  g_edges);

    // CSR build
    zero_cnt_kernel<<<(M + 255) / 256, 256>>>(cnt);
    hist_kernel<<<(E + 255) / 256, 256>>>(erow, cnt);
    scan_kernel<<<1, 1024>>>(cnt, rowptr, cursor);
    fill_kernel<<<(E + 255) / 256, 256>>>(erow, ecol, eval, cursor, edges);

    // Dense projection (tf32 tensor cores, double-buffered, fp16 output)
    gemm_kernel<<<(M + 127) / 128, 256>>>(x, W, xph);

    // Aggregate + ReLU (one warp per row; 8 warps per 256-thread block)
    {
        int warpsPerBlock = 256 / 32;
        int blocks = (M + warpsPerBlock - 1) / warpsPerBlock;  // 12500
        gather_kernel<<<blocks, 256>>>(rowptr, cnt, edges, xph, out);
    }
}

// round 10
// speedup vs baseline: 1.7343x; 1.1212x over previous
#include <cuda_runtime.h>
#include <cuda_bf16.h>
#include <cuda_fp16.h>
#include <cstddef>
#include <cstdint>

// Problem constants (fixed by the dataset)
constexpr int M = 100000;         // nodes
constexpr int K = 512;            // in_dim
constexpr int N = 128;            // out_dim
constexpr int E = 3200000;        // edges

// Device-global scratch (no allocations allowed).
__device__ __half g_xph[(size_t)M * N];   // 25.6 MB : xp = x @ W in fp16
__device__ __half g_wt[(size_t)N * K];    // W^T in fp16 [n][k]
__device__ int   g_cnt[M];                // degree histogram
__device__ int   g_rowptr[M];             // CSR row starts
__device__ int   g_cursor[M];             // fill cursors
__device__ int2  g_edges[E];              // packed {col, val-bits} in CSR order

// ---------------------------------------------------------------------------
// 1) zero the histogram
// ---------------------------------------------------------------------------
__global__ void zero_cnt_kernel(int* __restrict__ cnt) {
    int i = blockIdx.x * blockDim.x + threadIdx.x;
    if (i < M) cnt[i] = 0;
}

// ---------------------------------------------------------------------------
// 2) degree histogram over edge_row
// ---------------------------------------------------------------------------
__global__ void hist_kernel(const int* __restrict__ erow, int* __restrict__ cnt) {
    int i = blockIdx.x * blockDim.x + threadIdx.x;
    if (i < E) atomicAdd(&cnt[erow[i]], 1);
}

// ---------------------------------------------------------------------------
// 3) exclusive scan: 1024 threads, each owns a contiguous segment.
// ---------------------------------------------------------------------------
__global__ void scan_kernel(const int* __restrict__ cnt,
                            int* __restrict__ rowptr,
                            int* __restrict__ cursor) {
    __shared__ int sh[1024];
    const int tid = threadIdx.x;
    const int seg = (M + 1023) / 1024;           // 98
    const int base = tid * seg;
    const int end = min(M, base + seg);

    int s = 0;
    for (int i = base; i < end; i++) s += cnt[i];
    sh[tid] = s;
    __syncthreads();

    int v = s;
#pragma unroll
    for (int off = 1; off < 1024; off <<= 1) {
        int t = (tid >= off) ? sh[tid - off] : 0;
        __syncthreads();
        v += t;
        sh[tid] = v;
        __syncthreads();
    }
    int running = v - s;   // exclusive prefix for this segment

    for (int i = base; i < end; i++) {
        rowptr[i] = running;
        cursor[i] = running;
        running += cnt[i];
    }
}

// ---------------------------------------------------------------------------
// 4) fill CSR: scatter each edge into its row segment, packing {col, val}
// ---------------------------------------------------------------------------
__global__ void fill_kernel(const int* __restrict__ erow,
                            const int* __restrict__ ecol,
                            const float* __restrict__ eval,
                            int* __restrict__ cursor,
                            int2* __restrict__ edges) {
    int i = blockIdx.x * blockDim.x + threadIdx.x;
    if (i >= E) return;
    int r = erow[i];
    int pos = atomicAdd(&cursor[r], 1);
    edges[pos] = make_int2(ecol[i], __float_as_int(eval[i]));
}

// ---------------------------------------------------------------------------
// 4b) W transpose+convert: Wt[n][k] = fp16(W[k][n])
// ---------------------------------------------------------------------------
__global__ void wprep_kernel(const float* __restrict__ W,
                             __half* __restrict__ Wt) {
    int idx = blockIdx.x * blockDim.x + threadIdx.x;
    if (idx >= K * N) return;
    int n = idx & (N - 1);
    int k = idx >> 7;
    Wt[(size_t)n * K + k] = __float2half_rn(W[(size_t)k * N + n]);
}

// ---------------------------------------------------------------------------
// 5) fp16 tensor-core GEMM  xp[M,N] = X[M,K] @ W[K,N], fp16 output.
//    BM=128, BN=128, BK=32. mma.sync.m16n8k16.f16 with fp32 accum.
//    Double-buffered smem + register-staged prefetch.
//    A smem [m][k] halves, stride 40; B smem [n][k] halves, stride 40.
// ---------------------------------------------------------------------------
#define ASTR 40   // halves per A row (32 + 8 pad); 80 B, 16B-aligned
#define BSTR 40   // halves per B row

__global__ __launch_bounds__(256, 2)
void gemm_kernel(const float* __restrict__ X, const __half* __restrict__ Wt,
                 __half* __restrict__ XPh) {
    __shared__ __half As[2][128 * ASTR];
    __shared__ __half Bs[2][128 * BSTR];

    const int tid = threadIdx.x;
    const int lane = tid & 31;
    const int warpId = tid >> 5;
    const int warpM = warpId & 3;     // 0..3 -> 32-row slab
    const int warpN = warpId >> 2;    // 0..1 -> 64-col slab
    const int rowBlock = blockIdx.x * 128;

    float acc[2][8][4];
#pragma unroll
    for (int i = 0; i < 2; i++)
#pragma unroll
        for (int j = 0; j < 8; j++)
#pragma unroll
            for (int c = 0; c < 4; c++) acc[i][j][c] = 0.0f;

    const int quad = lane >> 2;       // 0..7
    const int qlan = lane & 3;        // 0..3

    // A-load mapping: 1024 tasks (row, 4-k group), 4 per thread
    //   idx = tid + it*256 : r = idx>>3 (0..127), kq = idx&7 (0..7)
    // B-load mapping: 512 tasks (n-row, 8-k group), 2 per thread
    //   idx = tid + it*256 : n = idx>>2 (0..127), g = idx&3
    float4 aReg[4];
    uint4  bReg[2];

    auto stage_store = [&](int buf) {
#pragma unroll
        for (int it = 0; it < 4; it++) {
            int idx = tid + it * 256;
            int r = idx >> 3;
            int kq = idx & 7;
            __half2 h0 = __floats2half2_rn(aReg[it].x, aReg[it].y);
            __half2 h1 = __floats2half2_rn(aReg[it].z, aReg[it].w);
            uint32_t u0 = *reinterpret_cast<uint32_t*>(&h0);
            uint32_t u1 = *reinterpret_cast<uint32_t*>(&h1);
            *reinterpret_cast<uint2*>(&As[buf][r * ASTR + kq * 4]) = make_uint2(u0, u1);
        }
#pragma unroll
        for (int it = 0; it < 2; it++) {
            int idx = tid + it * 256;
            int n = idx >> 2;
            int g = idx & 3;
            *reinterpret_cast<uint4*>(&Bs[buf][n * BSTR + g * 8]) = bReg[it];
        }
    };
    auto stage_load = [&](int k0) {
#pragma unroll
        for (int it = 0; it < 4; it++) {
            int idx = tid + it * 256;
            int r = idx >> 3;
            int kq = idx & 7;
            int gr = rowBlock + r;
            aReg[it] = (gr < M)
                ? *reinterpret_cast<const float4*>(&X[(size_t)gr * K + k0 + kq * 4])
                : make_float4(0.f, 0.f, 0.f, 0.f);
        }
#pragma unroll
        for (int it = 0; it < 2; it++) {
            int idx = tid + it * 256;
            int n = idx >> 2;
            int g = idx & 3;
            bReg[it] = *reinterpret_cast<const uint4*>(&Wt[(size_t)n * K + k0 + g * 8]);
        }
    };

    // ---- prologue ----
    stage_load(0);
    stage_store(0);
    __syncthreads();

    const int NITER = K / 32;   // 16
    for (int it = 0; it < NITER; it++) {
        const int buf = it & 1;
        const int nxt = buf ^ 1;

        if (it + 1 < NITER) stage_load((it + 1) * 32);

        // ---- compute current tile: 2 k16-steps ----
#pragma unroll
        for (int kk = 0; kk < 32; kk += 16) {
            // B fragments: 8 n-tiles of n8k16 (2 regs each)
            uint32_t bf[8][2];
#pragma unroll
            for (int j = 0; j < 8; j++) {
                int nrow = warpN * 64 + j * 8 + quad;
                bf[j][0] = *reinterpret_cast<const uint32_t*>(&Bs[buf][nrow * BSTR + kk + qlan * 2]);
                bf[j][1] = *reinterpret_cast<const uint32_t*>(&Bs[buf][nrow * BSTR + kk + qlan * 2 + 8]);
            }
            // A fragments: 2 m-tiles of m16k16 (4 regs each)
#pragma unroll
            for (int i = 0; i < 2; i++) {
                int row = warpM * 32 + i * 16 + quad;
                uint32_t a0 = *reinterpret_cast<const uint32_t*>(&As[buf][row * ASTR + kk + qlan * 2]);
                uint32_t a1 = *reinterpret_cast<const uint32_t*>(&As[buf][(row + 8) * ASTR + kk + qlan * 2]);
                uint32_t a2 = *reinterpret_cast<const uint32_t*>(&As[buf][row * ASTR + kk + qlan * 2 + 8]);
                uint32_t a3 = *reinterpret_cast<const uint32_t*>(&As[buf][(row + 8) * ASTR + kk + qlan * 2 + 8]);
#pragma unroll
                for (int j = 0; j < 8; j++) {
                    asm volatile(
                        "mma.sync.aligned.m16n8k16.row.col.f32.f16.f16.f32 "
                        "{%0,%1,%2,%3}, {%4,%5,%6,%7}, {%8,%9}, {%0,%1,%2,%3};\n"
                        : "+f"(acc[i][j][0]), "+f"(acc[i][j][1]),
                          "+f"(acc[i][j][2]), "+f"(acc[i][j][3])
                        : "r"(a0), "r"(a1), "r"(a2), "r"(a3),
                          "r"(bf[j][0]), "r"(bf[j][1]));
                }
            }
        }

        if (it + 1 < NITER) stage_store(nxt);
        __syncthreads();
    }

    // Epilogue: write fp16 results (c0,c1 and c2,c3 are contiguous col pairs)
#pragma unroll
    for (int i = 0; i < 2; i++) {
        int row0 = rowBlock + warpM * 32 + i * 16 + quad;
        int row1 = row0 + 8;
#pragma unroll
        for (int j = 0; j < 8; j++) {
            int col = warpN * 64 + j * 8 + qlan * 2;
            if (row0 < M)
                *reinterpret_cast<__half2*>(&XPh[(size_t)row0 * N + col]) =
                    __floats2half2_rn(acc[i][j][0], acc[i][j][1]);
            if (row1 < M)
                *reinterpret_cast<__half2*>(&XPh[(size_t)row1 * N + col]) =
                    __floats2half2_rn(acc[i][j][2], acc[i][j][3]);
        }
    }
}

// ---------------------------------------------------------------------------
// 6) gather-reduce + ReLU: one warp per row, 4 fp16 cols per lane (uint2),
//    2-edge unroll with dual accumulators; fp32 accumulate; fp32 store.
// ---------------------------------------------------------------------------
__global__ __launch_bounds__(256)
void gather_kernel(const int* __restrict__ rowptr,
                   const int* __restrict__ cnt,
                   const int2* __restrict__ edges,
                   const __half* __restrict__ xp,
                   float* __restrict__ out) {
    int warp = (blockIdx.x * blockDim.x + threadIdx.x) >> 5;
    if (warp >= M) return;
    int lane = threadIdx.x & 31;

    int start = rowptr[warp];
    int deg   = cnt[warp];

    float4 acc0 = make_float4(0.f, 0.f, 0.f, 0.f);
    float4 acc1 = make_float4(0.f, 0.f, 0.f, 0.f);

    int t = 0;
    for (; t + 1 < deg; t += 2) {
        int2 ev0 = edges[start + t];
        int2 ev1 = edges[start + t + 1];
        float v0 = __int_as_float(ev0.y);
        float v1 = __int_as_float(ev1.y);
        uint2 u0 = *reinterpret_cast<const uint2*>(&xp[(size_t)ev0.x * N + lane * 4]);
        uint2 u1 = *reinterpret_cast<const uint2*>(&xp[(size_t)ev1.x * N + lane * 4]);
        float2 a0 = __half22float2(*reinterpret_cast<__half2*>(&u0.x));
        float2 b0 = __half22float2(*reinterpret_cast<__half2*>(&u0.y));
        float2 a1 = __half22float2(*reinterpret_cast<__half2*>(&u1.x));
        float2 b1 = __half22float2(*reinterpret_cast<__half2*>(&u1.y));
        acc0.x = fmaf(v0, a0.x, acc0.x);
        acc0.y = fmaf(v0, a0.y, acc0.y);
        acc0.z = fmaf(v0, b0.x, acc0.z);
        acc0.w = fmaf(v0, b0.y, acc0.w);
        acc1.x = fmaf(v1, a1.x, acc1.x);
        acc1.y = fmaf(v1, a1.y, acc1.y);
        acc1.z = fmaf(v1, b1.x, acc1.z);
        acc1.w = fmaf(v1, b1.y, acc1.w);
    }
    if (t < deg) {
        int2 ev = edges[start + t];
        float v = __int_as_float(ev.y);
        uint2 u = *reinterpret_cast<const uint2*>(&xp[(size_t)ev.x * N + lane * 4]);
        float2 a = __half22float2(*reinterpret_cast<__half2*>(&u.x));
        float2 b = __half22float2(*reinterpret_cast<__half2*>(&u.y));
        acc0.x = fmaf(v, a.x, acc0.x);
        acc0.y = fmaf(v, a.y, acc0.y);
        acc0.z = fmaf(v, b.x, acc0.z);
        acc0.w = fmaf(v, b.y, acc0.w);
    }

    float4 r = make_float4(fmaxf(acc0.x + acc1.x, 0.f),
                           fmaxf(acc0.y + acc1.y, 0.f),
                           fmaxf(acc0.z + acc1.z, 0.f),
                           fmaxf(acc0.w + acc1.w, 0.f));
    *reinterpret_cast<float4*>(&out[(size_t)warp * N + lane * 4]) = r;
}

// ---------------------------------------------------------------------------
extern "C" void kernel_launch(void* const* d_in, const int* in_sizes, int n_in,
                              void* d_out, int out_size) {
    const float* x    = (const float*)d_in[0];   // [M,K]
    const float* W    = (const float*)d_in[1];   // [K,N]
    const int*   erow = (const int*)d_in[2];     // [E]
    const int*   ecol = (const int*)d_in[3];     // [E]
    const float* eval = (const float*)d_in[4];   // [E]
    float* out = (float*)d_out;                  // [M,N]

    __half* xph;   cudaGetSymbolAddress((void**)&xph,    g_xph);
    __half* wt;    cudaGetSymbolAddress((void**)&wt,     g_wt);
    int*  cnt;     cudaGetSymbolAddress((void**)&cnt,    g_cnt);
    int*  rowptr;  cudaGetSymbolAddress((void**)&rowptr, g_rowptr);
    int*  cursor;  cudaGetSymbolAddress((void**)&cursor, g_cursor);
    int2* edges;   cudaGetSymbolAddress((void**)&edges,  g_edges);

    // CSR build
    zero_cnt_kernel<<<(M + 255) / 256, 256>>>(cnt);
    hist_kernel<<<(E + 255) / 256, 256>>>(erow, cnt);
    scan_kernel<<<1, 1024>>>(cnt, rowptr, cursor);
    fill_kernel<<<(E + 255) / 256, 256>>>(erow, ecol, eval, cursor, edges);

    // W transpose + fp16 convert, then dense projection (fp16 HMMA)
    wprep_kernel<<<(K * N + 255) / 256, 256>>>(W, wt);
    gemm_kernel<<<(M + 127) / 128, 256>>>(x, wt, xph);

    // Aggregate + ReLU (one warp per row; 8 warps per 256-thread block)
    {
        int warpsPerBlock = 256 / 32;
        int blocks = (M + warpsPerBlock - 1) / warpsPerBlock;  // 12500
        gather_kernel<<<blocks, 256>>>(rowptr, cnt, edges, xph, out);
    }
}

// round 11
// speedup vs baseline: 2.0833x; 1.2012x over previous
#include <cuda_runtime.h>
#include <cuda_bf16.h>
#include <cuda_fp16.h>
#include <cstddef>
#include <cstdint>

// Problem constants (fixed by the dataset)
constexpr int M = 100000;         // nodes
constexpr int K = 512;            // in_dim
constexpr int N = 128;            // out_dim
constexpr int E = 3200000;        // edges

// Device-global scratch (no allocations allowed).
__device__ __half g_xph[(size_t)M * N];   // 25.6 MB : xp = x @ W in fp16
__device__ __half g_wt[(size_t)N * K];    // W^T in fp16 [n][k]
__device__ int   g_cnt[M];                // degree histogram
__device__ int   g_rowptr[M];             // CSR row starts
__device__ int   g_cursor[M];             // fill cursors
__device__ int2  g_edges[E];              // packed {col, val-bits} in CSR order

// ---------------------------------------------------------------------------
// 1) zero the histogram
// ---------------------------------------------------------------------------
__global__ void zero_cnt_kernel(int* __restrict__ cnt) {
    int i = blockIdx.x * blockDim.x + threadIdx.x;
    if (i < M) cnt[i] = 0;
}

// ---------------------------------------------------------------------------
// 2) degree histogram over edge_row
// ---------------------------------------------------------------------------
__global__ void hist_kernel(const int* __restrict__ erow, int* __restrict__ cnt) {
    int i = blockIdx.x * blockDim.x + threadIdx.x;
    if (i < E) atomicAdd(&cnt[erow[i]], 1);
}

// ---------------------------------------------------------------------------
// 3) exclusive scan: 1024 threads, each owns a contiguous segment.
// ---------------------------------------------------------------------------
__global__ void scan_kernel(const int* __restrict__ cnt,
                            int* __restrict__ rowptr,
                            int* __restrict__ cursor) {
    __shared__ int sh[1024];
    const int tid = threadIdx.x;
    const int seg = (M + 1023) / 1024;           // 98
    const int base = tid * seg;
    const int end = min(M, base + seg);

    int s = 0;
    for (int i = base; i < end; i++) s += cnt[i];
    sh[tid] = s;
    __syncthreads();

    int v = s;
#pragma unroll
    for (int off = 1; off < 1024; off <<= 1) {
        int t = (tid >= off) ? sh[tid - off] : 0;
        __syncthreads();
        v += t;
        sh[tid] = v;
        __syncthreads();
    }
    int running = v - s;   // exclusive prefix for this segment

    for (int i = base; i < end; i++) {
        rowptr[i] = running;
        cursor[i] = running;
        running += cnt[i];
    }
}

// ---------------------------------------------------------------------------
// 4) fill CSR: scatter each edge into its row segment, packing {col, val}
// ---------------------------------------------------------------------------
__global__ void fill_kernel(const int* __restrict__ erow,
                            const int* __restrict__ ecol,
                            const float* __restrict__ eval,
                            int* __restrict__ cursor,
                            int2* __restrict__ edges) {
    int i = blockIdx.x * blockDim.x + threadIdx.x;
    if (i >= E) return;
    int r = erow[i];
    int pos = atomicAdd(&cursor[r], 1);
    edges[pos] = make_int2(ecol[i], __float_as_int(eval[i]));
}

// ---------------------------------------------------------------------------
// 4b) W transpose+convert: Wt[n][k] = fp16(W[k][n])
// ---------------------------------------------------------------------------
__global__ void wprep_kernel(const float* __restrict__ W,
                             __half* __restrict__ Wt) {
    int idx = blockIdx.x * blockDim.x + threadIdx.x;
    if (idx >= K * N) return;
    int n = idx & (N - 1);
    int k = idx >> 7;
    Wt[(size_t)n * K + k] = __float2half_rn(W[(size_t)k * N + n]);
}

// ---------------------------------------------------------------------------
// 5) fp16 tensor-core GEMM  xp[M,N] = X[M,K] @ W[K,N], fp16 output.
//    BM=128, BN=128, BK=32. mma.sync.m16n8k16.f16 with fp32 accum.
//    Double-buffered smem + register-staged prefetch.
// ---------------------------------------------------------------------------
#define ASTR 40   // halves per A row (32 + 8 pad); 80 B, 16B-aligned
#define BSTR 40   // halves per B row

__global__ __launch_bounds__(256, 2)
void gemm_kernel(const float* __restrict__ X, const __half* __restrict__ Wt,
                 __half* __restrict__ XPh) {
    __shared__ __half As[2][128 * ASTR];
    __shared__ __half Bs[2][128 * BSTR];

    const int tid = threadIdx.x;
    const int lane = tid & 31;
    const int warpId = tid >> 5;
    const int warpM = warpId & 3;     // 0..3 -> 32-row slab
    const int warpN = warpId >> 2;    // 0..1 -> 64-col slab
    const int rowBlock = blockIdx.x * 128;

    float acc[2][8][4];
#pragma unroll
    for (int i = 0; i < 2; i++)
#pragma unroll
        for (int j = 0; j < 8; j++)
#pragma unroll
            for (int c = 0; c < 4; c++) acc[i][j][c] = 0.0f;

    const int quad = lane >> 2;       // 0..7
    const int qlan = lane & 3;        // 0..3

    float4 aReg[4];
    uint4  bReg[2];

    auto stage_store = [&](int buf) {
#pragma unroll
        for (int it = 0; it < 4; it++) {
            int idx = tid + it * 256;
            int r = idx >> 3;
            int kq = idx & 7;
            __half2 h0 = __floats2half2_rn(aReg[it].x, aReg[it].y);
            __half2 h1 = __floats2half2_rn(aReg[it].z, aReg[it].w);
            uint32_t u0 = *reinterpret_cast<uint32_t*>(&h0);
            uint32_t u1 = *reinterpret_cast<uint32_t*>(&h1);
            *reinterpret_cast<uint2*>(&As[buf][r * ASTR + kq * 4]) = make_uint2(u0, u1);
        }
#pragma unroll
        for (int it = 0; it < 2; it++) {
            int idx = tid + it * 256;
            int n = idx >> 2;
            int g = idx & 3;
            *reinterpret_cast<uint4*>(&Bs[buf][n * BSTR + g * 8]) = bReg[it];
        }
    };
    auto stage_load = [&](int k0) {
#pragma unroll
        for (int it = 0; it < 4; it++) {
            int idx = tid + it * 256;
            int r = idx >> 3;
            int kq = idx & 7;
            int gr = rowBlock + r;
            aReg[it] = (gr < M)
                ? *reinterpret_cast<const float4*>(&X[(size_t)gr * K + k0 + kq * 4])
                : make_float4(0.f, 0.f, 0.f, 0.f);
        }
#pragma unroll
        for (int it = 0; it < 2; it++) {
            int idx = tid + it * 256;
            int n = idx >> 2;
            int g = idx & 3;
            bReg[it] = *reinterpret_cast<const uint4*>(&Wt[(size_t)n * K + k0 + g * 8]);
        }
    };

    // ---- prologue ----
    stage_load(0);
    stage_store(0);
    __syncthreads();

    const int NITER = K / 32;   // 16
    for (int it = 0; it < NITER; it++) {
        const int buf = it & 1;
        const int nxt = buf ^ 1;

        if (it + 1 < NITER) stage_load((it + 1) * 32);

        // ---- compute current tile: 2 k16-steps ----
#pragma unroll
        for (int kk = 0; kk < 32; kk += 16) {
            uint32_t bf[8][2];
#pragma unroll
            for (int j = 0; j < 8; j++) {
                int nrow = warpN * 64 + j * 8 + quad;
                bf[j][0] = *reinterpret_cast<const uint32_t*>(&Bs[buf][nrow * BSTR + kk + qlan * 2]);
                bf[j][1] = *reinterpret_cast<const uint32_t*>(&Bs[buf][nrow * BSTR + kk + qlan * 2 + 8]);
            }
#pragma unroll
            for (int i = 0; i < 2; i++) {
                int row = warpM * 32 + i * 16 + quad;
                uint32_t a0 = *reinterpret_cast<const uint32_t*>(&As[buf][row * ASTR + kk + qlan * 2]);
                uint32_t a1 = *reinterpret_cast<const uint32_t*>(&As[buf][(row + 8) * ASTR + kk + qlan * 2]);
                uint32_t a2 = *reinterpret_cast<const uint32_t*>(&As[buf][row * ASTR + kk + qlan * 2 + 8]);
                uint32_t a3 = *reinterpret_cast<const uint32_t*>(&As[buf][(row + 8) * ASTR + kk + qlan * 2 + 8]);
#pragma unroll
                for (int j = 0; j < 8; j++) {
                    asm volatile(
                        "mma.sync.aligned.m16n8k16.row.col.f32.f16.f16.f32 "
                        "{%0,%1,%2,%3}, {%4,%5,%6,%7}, {%8,%9}, {%0,%1,%2,%3};\n"
                        : "+f"(acc[i][j][0]), "+f"(acc[i][j][1]),
                          "+f"(acc[i][j][2]), "+f"(acc[i][j][3])
                        : "r"(a0), "r"(a1), "r"(a2), "r"(a3),
                          "r"(bf[j][0]), "r"(bf[j][1]));
                }
            }
        }

        if (it + 1 < NITER) stage_store(nxt);
        __syncthreads();
    }

    // Epilogue: write fp16 results
#pragma unroll
    for (int i = 0; i < 2; i++) {
        int row0 = rowBlock + warpM * 32 + i * 16 + quad;
        int row1 = row0 + 8;
#pragma unroll
        for (int j = 0; j < 8; j++) {
            int col = warpN * 64 + j * 8 + qlan * 2;
            if (row0 < M)
                *reinterpret_cast<__half2*>(&XPh[(size_t)row0 * N + col]) =
                    __floats2half2_rn(acc[i][j][0], acc[i][j][1]);
            if (row1 < M)
                *reinterpret_cast<__half2*>(&XPh[(size_t)row1 * N + col]) =
                    __floats2half2_rn(acc[i][j][2], acc[i][j][3]);
        }
    }
}

// ---------------------------------------------------------------------------
// 6) gather-reduce + ReLU: one warp per row, 4 fp16 cols per lane (uint2),
//    2-edge unroll with dual accumulators; fp32 accumulate; fp32 store.
// ---------------------------------------------------------------------------
__global__ __launch_bounds__(256)
void gather_kernel(const int* __restrict__ rowptr,
                   const int* __restrict__ cnt,
                   const int2* __restrict__ edges,
                   const __half* __restrict__ xp,
                   float* __restrict__ out) {
    int warp = (blockIdx.x * blockDim.x + threadIdx.x) >> 5;
    if (warp >= M) return;
    int lane = threadIdx.x & 31;

    int start = rowptr[warp];
    int deg   = cnt[warp];

    float4 acc0 = make_float4(0.f, 0.f, 0.f, 0.f);
    float4 acc1 = make_float4(0.f, 0.f, 0.f, 0.f);

    int t = 0;
    for (; t + 1 < deg; t += 2) {
        int2 ev0 = edges[start + t];
        int2 ev1 = edges[start + t + 1];
        float v0 = __int_as_float(ev0.y);
        float v1 = __int_as_float(ev1.y);
        uint2 u0 = *reinterpret_cast<const uint2*>(&xp[(size_t)ev0.x * N + lane * 4]);
        uint2 u1 = *reinterpret_cast<const uint2*>(&xp[(size_t)ev1.x * N + lane * 4]);
        float2 a0 = __half22float2(*reinterpret_cast<__half2*>(&u0.x));
        float2 b0 = __half22float2(*reinterpret_cast<__half2*>(&u0.y));
        float2 a1 = __half22float2(*reinterpret_cast<__half2*>(&u1.x));
        float2 b1 = __half22float2(*reinterpret_cast<__half2*>(&u1.y));
        acc0.x = fmaf(v0, a0.x, acc0.x);
        acc0.y = fmaf(v0, a0.y, acc0.y);
        acc0.z = fmaf(v0, b0.x, acc0.z);
        acc0.w = fmaf(v0, b0.y, acc0.w);
        acc1.x = fmaf(v1, a1.x, acc1.x);
        acc1.y = fmaf(v1, a1.y, acc1.y);
        acc1.z = fmaf(v1, b1.x, acc1.z);
        acc1.w = fmaf(v1, b1.y, acc1.w);
    }
    if (t < deg) {
        int2 ev = edges[start + t];
        float v = __int_as_float(ev.y);
        uint2 u = *reinterpret_cast<const uint2*>(&xp[(size_t)ev.x * N + lane * 4]);
        float2 a = __half22float2(*reinterpret_cast<__half2*>(&u.x));
        float2 b = __half22float2(*reinterpret_cast<__half2*>(&u.y));
        acc0.x = fmaf(v, a.x, acc0.x);
        acc0.y = fmaf(v, a.y, acc0.y);
        acc0.z = fmaf(v, b.x, acc0.z);
        acc0.w = fmaf(v, b.y, acc0.w);
    }

    float4 r = make_float4(fmaxf(acc0.x + acc1.x, 0.f),
                           fmaxf(acc0.y + acc1.y, 0.f),
                           fmaxf(acc0.z + acc1.z, 0.f),
                           fmaxf(acc0.w + acc1.w, 0.f));
    *reinterpret_cast<float4*>(&out[(size_t)warp * N + lane * 4]) = r;
}

// ---------------------------------------------------------------------------
// Launch topology: fork the independent CSR build onto a side stream so it
// overlaps the GEMM chain; join before gather. Standard graph-capture
// fork/join pattern (event record on capture stream -> side-stream wait ->
// work -> event join). Streams/events are host-side resources (no device
// allocation); left undestroyed to keep captured graph nodes valid.
// ---------------------------------------------------------------------------
extern "C" void kernel_launch(void* const* d_in, const int* in_sizes, int n_in,
                              void* d_out, int out_size) {
    const float* x    = (const float*)d_in[0];   // [M,K]
    const float* W    = (const float*)d_in[1];   // [K,N]
    const int*   erow = (const int*)d_in[2];     // [E]
    const int*   ecol = (const int*)d_in[3];     // [E]
    const float* eval = (const float*)d_in[4];   // [E]
    float* out = (float*)d_out;                  // [M,N]

    __half* xph;   cudaGetSymbolAddress((void**)&xph,    g_xph);
    __half* wt;    cudaGetSymbolAddress((void**)&wt,     g_wt);
    int*  cnt;     cudaGetSymbolAddress((void**)&cnt,    g_cnt);
    int*  rowptr;  cudaGetSymbolAddress((void**)&rowptr, g_rowptr);
    int*  cursor;  cudaGetSymbolAddress((void**)&cursor, g_cursor);
    int2* edges;   cudaGetSymbolAddress((void**)&edges,  g_edges);

    cudaStream_t s1;
    cudaEvent_t eFork, eJoin;
    cudaStreamCreateWithFlags(&s1, cudaStreamNonBlocking);
    cudaEventCreateWithFlags(&eFork, cudaEventDisableTiming);
    cudaEventCreateWithFlags(&eJoin, cudaEventDisableTiming);

    // fork: side stream depends on the capture (default) stream's front
    cudaEventRecord(eFork, (cudaStream_t)0);
    cudaStreamWaitEvent(s1, eFork, 0);

    // --- CSR build on side stream (independent of x/W) ---
    zero_cnt_kernel<<<(M + 255) / 256, 256, 0, s1>>>(cnt);
    hist_kernel<<<(E + 255) / 256, 256, 0, s1>>>(erow, cnt);
    scan_kernel<<<1, 1024, 0, s1>>>(cnt, rowptr, cursor);
    fill_kernel<<<(E + 255) / 256, 256, 0, s1>>>(erow, ecol, eval, cursor, edges);
    cudaEventRecord(eJoin, s1);

    // --- GEMM chain on default stream (overlaps CSR build) ---
    wprep_kernel<<<(K * N + 255) / 256, 256>>>(W, wt);
    gemm_kernel<<<(M + 127) / 128, 256>>>(x, wt, xph);

    // join: gather needs both xph and the CSR
    cudaStreamWaitEvent((cudaStream_t)0, eJoin, 0);
    {
        int warpsPerBlock = 256 / 32;
        int blocks = (M + warpsPerBlock - 1) / warpsPerBlock;  // 12500
        gather_kernel<<<blocks, 256>>>(rowptr, cnt, edges, xph, out);
    }
}